// round 7
// baseline (speedup 1.0000x reference)
#include <cuda_runtime.h>
#include <cstdint>

// Problem constants
#define NROWS   24000          // BS*Q
#define NTGT    2400           // BS*NT
#define KCLS    256
#define R_TILE  16             // rows per block in main kernel (16 -> ~16.6KB smem, high occ)
#define TPT     5              // targets per thread (strided by BLOCK)
#define BLOCK   160            // 5 warps
#define TT      (BLOCK*TPT)    // 800 targets per block-group
#define NGROUPS 3              // 3 * 800 = 2400 exactly -> zero lane waste

// Scratch (allocation-free: __device__ global)
__device__ float g_diff[NROWS * KCLS];     // focal class cost diff + 2.0

// ---------------------------------------------------------------------------
// Kernel 1: per-(n,k) focal classification cost diff' = pos - neg + 2
//   Uses ln(p) = -ln(1+e^{-x}), ln(1-p) = -x - ln(1+e^{-x})  (3 MUFU not 4)
//   float4 vectorized: each thread does 4 elements.
// ---------------------------------------------------------------------------
__global__ void k_diff(const float* __restrict__ logits) {
    int i = blockIdx.x * blockDim.x + threadIdx.x;   // i indexes float4
    float4 x4 = ((const float4*)logits)[i];
    float r[4];
    float xs[4] = {x4.x, x4.y, x4.z, x4.w};
    #pragma unroll
    for (int k = 0; k < 4; k++) {
        float x = xs[k];
        float e = __expf(-x);
        float a = 1.0f + e;
        float s = __logf(a);          // = -ln(p) = softplus(-x)
        float p;
        asm("rcp.approx.f32 %0, %1;" : "=f"(p) : "f"(a));   // sigmoid
        float omp = 1.0f - p;
        // pos = 0.25*(1-p)^2 * (-ln p);  neg = 0.75*p^2 * (x + s)
        float pos = (omp * omp) * (0.25f * s);
        float neg = (p * p) * (0.75f * (x + s));
        r[k] = (pos - neg) + 2.0f;    // fold GIoU's "+2" constant in
    }
    ((float4*)g_diff)[i] = make_float4(r[0], r[1], r[2], r[3]);
}

// ---------------------------------------------------------------------------
// Kernel 2: main pair kernel. Block = 16 rows x 800 targets (strided TPT=5).
// Symmetric-interval identity with HALF-widths (w2 = 0.5*w):
//   mx      = max(|rcx-tcx|, |rw2-tw2|)
//   inter_w = (rw2+tw2) - mx   (clamped >= 0)
//   encl_w  = (rw2+tw2) + mx
// ---------------------------------------------------------------------------
__global__ __launch_bounds__(BLOCK) void k_main(const float* __restrict__ pboxes,
                                                const float* __restrict__ tboxes,
                                                const int* __restrict__ tids,
                                                float* __restrict__ out) {
    __shared__ float4 sbox[R_TILE];           // {cx, cy, 0.5w, 0.5h}
    __shared__ float  sarea[R_TILE];
    __shared__ float  sdiff[R_TILE * KCLS];   // 16 KB

    const int tid   = threadIdx.x;
    const int r0    = blockIdx.x * R_TILE;
    const int tbase = blockIdx.y * TT + tid;   // thread's first target; stride BLOCK

    // Stage row boxes (half-extents) + areas
    if (tid < R_TILE) {
        float4 b = ((const float4*)pboxes)[r0 + tid];
        sarea[tid] = b.z * b.w;
        sbox[tid]  = make_float4(b.x, b.y, 0.5f * b.z, 0.5f * b.w);
    }
    // Stage diff rows: 16*256 floats = 1024 float4
    {
        const float4* gd  = (const float4*)(g_diff + (size_t)r0 * KCLS);
        float4*       sd4 = (float4*)sdiff;
        for (int i = tid; i < (R_TILE * KCLS) / 4; i += BLOCK)
            sd4[i] = gd[i];
    }

    // Target data -> registers (constant across row loop). All slots valid.
    float tcx[TPT], tcy[TPT], tw2[TPT], th2[TPT], tarea[TPT];
    int   cof[TPT];
    #pragma unroll
    for (int j = 0; j < TPT; j++) {
        int t = tbase + j * BLOCK;
        float4 b = ((const float4*)tboxes)[t];
        tcx[j] = b.x; tcy[j] = b.y;
        tw2[j] = 0.5f * b.z; th2[j] = 0.5f * b.w;
        tarea[j] = b.z * b.w;
        cof[j] = tids[t];
    }
    __syncthreads();

    float* op = out + (size_t)r0 * NTGT + tbase;

    #pragma unroll 1
    for (int r = 0; r < R_TILE; r++) {
        const float4 ra = sbox[r];        // cx cy w2 h2
        const float  rarea = sarea[r];
        const float* drow = sdiff + r * KCLS;
        float su[TPT];
        #pragma unroll
        for (int j = 0; j < TPT; j++) su[j] = rarea + tarea[j];
        #pragma unroll
        for (int j = 0; j < TPT; j++) {
            float d = drow[cof[j]];                        // class cost (+2)
            float adx  = fabsf(ra.x - tcx[j]);
            float ady  = fabsf(ra.y - tcy[j]);
            float adwh = fabsf(ra.z - tw2[j]);             // = 0.5*|dw|
            float adhh = fabsf(ra.w - th2[j]);             // = 0.5*|dh|
            // L1 on cxcywh: |dx|+|dy| + 2*(|dw|/2 + |dh|/2)
            float bb = __fmaf_rn(2.0f, adwh + adhh, adx + ady);
            // half-extent sums and the max terms
            float sw2 = ra.z + tw2[j];
            float sh2 = ra.w + th2[j];
            float mxx = fmaxf(adx, adwh);
            float mxy = fmaxf(ady, adhh);
            // intersection / enclosing extents
            float iw = fmaxf(sw2 - mxx, 0.0f);
            float ih = fmaxf(sh2 - mxy, 0.0f);
            float ew = sw2 + mxx;
            float eh = sh2 + mxy;
            float inter = iw * ih;
            float uni   = su[j] - inter;
            float ea    = ew * eh;
            float ru, re;
            asm("rcp.approx.f32 %0, %1;" : "=f"(ru) : "f"(uni));
            asm("rcp.approx.f32 %0, %1;" : "=f"(re) : "f"(ea));
            // C = 5*bb + (class+2) - 2*(inter/uni + uni/ea)
            float t1 = uni * re;
            t1 = __fmaf_rn(inter, ru, t1);
            float c = __fmaf_rn(5.0f, bb, d);
            c = __fmaf_rn(-2.0f, t1, c);
            op[j * BLOCK] = c;
        }
        op += NTGT;
    }
}

// ---------------------------------------------------------------------------
extern "C" void kernel_launch(void* const* d_in, const int* in_sizes, int n_in,
                              void* d_out, int out_size) {
    const float* logits = (const float*)d_in[0];   // [16,1500,256]
    const float* pboxes = (const float*)d_in[1];   // [24000,4]
    const float* tboxes = (const float*)d_in[2];   // [2400,4]
    const int*   tids   = (const int*)  d_in[3];   // [2400]
    float* out = (float*)d_out;

    // 6,144,000 elements / 4 per thread / 256 per block = 6000 blocks
    k_diff<<<(NROWS * KCLS) / 4 / 256, 256>>>(logits);

    dim3 grid(NROWS / R_TILE, NGROUPS);
    k_main<<<grid, BLOCK>>>(pboxes, tboxes, tids, out);
}

// round 9
// speedup vs baseline: 1.5951x; 1.5951x over previous
#include <cuda_runtime.h>
#include <cstdint>

// Problem constants
#define NROWS   24000          // BS*Q
#define NTGT    2400           // BS*NT
#define KCLS    256
#define R_TILE  30             // rows per block: grid = 800*3 = 2400 -> 2.70 waves @ C=888
#define TPT     5              // targets per thread (strided by BLOCK)
#define BLOCK   160            // 5 warps
#define TT      (BLOCK*TPT)    // 800 targets per block-group
#define NGROUPS 3              // 3 * 800 = 2400 exactly -> zero lane waste
// Pad sdiff so block smem ~33.5KB: forces exactly 6 blocks/SM (228/33.5 = 6.8 -> 6).
// 7 blocks/SM would give C=1036 -> 2400/1036=2.32 -> 3 waves (worse wave efficiency).
#define SDIFF_ELEMS 8448       // 33 KB (used: 30*256 = 7680)

// Scratch (allocation-free: __device__ global)
__device__ float g_diff[NROWS * KCLS];     // focal class cost diff + 2.0

// ---------------------------------------------------------------------------
// Kernel 1: per-(n,k) focal classification cost diff' = pos - neg + 2
//   ln(p) = -ln(1+e^{-x}), ln(1-p) = -x - ln(1+e^{-x})  (3 MUFU not 4)
// ---------------------------------------------------------------------------
__global__ void k_diff(const float* __restrict__ logits) {
    int i = blockIdx.x * blockDim.x + threadIdx.x;   // i indexes float4
    float4 x4 = ((const float4*)logits)[i];
    float r[4];
    float xs[4] = {x4.x, x4.y, x4.z, x4.w};
    #pragma unroll
    for (int k = 0; k < 4; k++) {
        float x = xs[k];
        float e = __expf(-x);
        float a = 1.0f + e;
        float s = __logf(a);          // = -ln(p) = softplus(-x)
        float p;
        asm("rcp.approx.f32 %0, %1;" : "=f"(p) : "f"(a));   // sigmoid
        float omp = 1.0f - p;
        float pos = (omp * omp) * (0.25f * s);
        float neg = (p * p) * (0.75f * (x + s));
        r[k] = (pos - neg) + 2.0f;    // fold GIoU's "+2" constant in
    }
    ((float4*)g_diff)[i] = make_float4(r[0], r[1], r[2], r[3]);
}

// ---------------------------------------------------------------------------
// Kernel 2: main pair kernel. Block = 30 rows x 800 targets (strided TPT=5).
// Symmetric-interval identity with HALF-widths (w2 = 0.5*w):
//   mx      = max(|rcx-tcx|, |rw2-tw2|)
//   inter_w = (rw2+tw2) - mx   (clamped via SAT: always < 1)
//   encl_w  = (rw2+tw2) + mx
// ---------------------------------------------------------------------------
__global__ __launch_bounds__(BLOCK) void k_main(const float* __restrict__ pboxes,
                                                const float* __restrict__ tboxes,
                                                const int* __restrict__ tids,
                                                float* __restrict__ out) {
    // NOTE: sdiff MUST be 16B-aligned: it's accessed via float4*.
    // (R_TILE=30 makes sbox+sarea = 600 B, which is not 16B-aligned by itself.)
    __shared__ __align__(16) float  sdiff[SDIFF_ELEMS];   // 33 KB (padded: occupancy pin)
    __shared__ __align__(16) float4 sbox[R_TILE];         // {cx, cy, 0.5w, 0.5h}
    __shared__ float  sarea[R_TILE];

    const int tid   = threadIdx.x;
    const int r0    = blockIdx.x * R_TILE;
    const int tbase = blockIdx.y * TT + tid;   // thread's first target; stride BLOCK

    // Stage row boxes (half-extents) + areas
    if (tid < R_TILE) {
        float4 b = ((const float4*)pboxes)[r0 + tid];
        sarea[tid] = b.z * b.w;
        sbox[tid]  = make_float4(b.x, b.y, 0.5f * b.z, 0.5f * b.w);
    }
    // Stage diff rows: 30*256 floats = 1920 float4 -> exactly 12 per thread
    {
        const float4* gd  = (const float4*)(g_diff + (size_t)r0 * KCLS);
        float4*       sd4 = (float4*)sdiff;
        #pragma unroll
        for (int i = 0; i < (R_TILE * KCLS / 4) / BLOCK; i++)
            sd4[tid + i * BLOCK] = gd[tid + i * BLOCK];
    }

    // Target data -> registers (constant across row loop). All slots valid.
    float tcx[TPT], tcy[TPT], tw2[TPT], th2[TPT], tarea[TPT];
    int   cof[TPT];
    #pragma unroll
    for (int j = 0; j < TPT; j++) {
        int t = tbase + j * BLOCK;
        float4 b = ((const float4*)tboxes)[t];
        tcx[j] = b.x; tcy[j] = b.y;
        tw2[j] = 0.5f * b.z; th2[j] = 0.5f * b.w;
        tarea[j] = b.z * b.w;
        cof[j] = tids[t];
    }
    __syncthreads();

    float* op = out + (size_t)r0 * NTGT + tbase;

    #pragma unroll 1
    for (int r = 0; r < R_TILE; r++) {
        const float4 ra = sbox[r];        // cx cy w2 h2
        const float  rarea = sarea[r];
        const float* drow = sdiff + r * KCLS;
        #pragma unroll
        for (int j = 0; j < TPT; j++) {
            float d = drow[cof[j]];                        // class cost (+2)
            float adx  = fabsf(ra.x - tcx[j]);
            float ady  = fabsf(ra.y - tcy[j]);
            float adwh = fabsf(ra.z - tw2[j]);             // = 0.5*|dw|
            float adhh = fabsf(ra.w - th2[j]);             // = 0.5*|dh|
            // L1 on cxcywh: |dx|+|dy| + 2*(|dw|/2 + |dh|/2)
            float bb = __fmaf_rn(2.0f, adwh + adhh, adx + ady);
            // half-extent sums and the max terms
            float sw2 = ra.z + tw2[j];
            float sh2 = ra.w + th2[j];
            float mxx = fmaxf(adx, adwh);
            float mxy = fmaxf(ady, adhh);
            // intersection / enclosing extents (SAT clamp: extents always < 1)
            float iw = __saturatef(sw2 - mxx);
            float ih = __saturatef(sh2 - mxy);
            float ew = sw2 + mxx;
            float eh = sh2 + mxy;
            float inter = iw * ih;
            float uni   = (rarea + tarea[j]) - inter;
            float ea    = ew * eh;
            float ru, re;
            asm("rcp.approx.f32 %0, %1;" : "=f"(ru) : "f"(uni));
            asm("rcp.approx.f32 %0, %1;" : "=f"(re) : "f"(ea));
            // C = 5*bb + (class+2) - 2*(inter/uni + uni/ea)
            float t1 = uni * re;
            t1 = __fmaf_rn(inter, ru, t1);
            float c = __fmaf_rn(5.0f, bb, d);
            c = __fmaf_rn(-2.0f, t1, c);
            op[j * BLOCK] = c;
        }
        op += NTGT;
    }
}

// ---------------------------------------------------------------------------
extern "C" void kernel_launch(void* const* d_in, const int* in_sizes, int n_in,
                              void* d_out, int out_size) {
    const float* logits = (const float*)d_in[0];   // [16,1500,256]
    const float* pboxes = (const float*)d_in[1];   // [24000,4]
    const float* tboxes = (const float*)d_in[2];   // [2400,4]
    const int*   tids   = (const int*)  d_in[3];   // [2400]
    float* out = (float*)d_out;

    k_diff<<<(NROWS * KCLS) / 4 / 256, 256>>>(logits);

    dim3 grid(NROWS / R_TILE, NGROUPS);
    k_main<<<grid, BLOCK>>>(pboxes, tboxes, tids, out);
}

// round 11
// speedup vs baseline: 1.6976x; 1.0643x over previous
#include <cuda_runtime.h>
#include <cstdint>

// Problem constants
#define NROWS   24000          // BS*Q
#define NTGT    2400           // BS*NT
#define KCLS    256
#define R_TILE  30             // rows per block: grid = 800*3 = 2400 -> 2.70 waves @ C=888
#define TPT     5              // targets per thread (strided by BLOCK)
#define BLOCK   160            // 5 warps
#define TT      (BLOCK*TPT)    // 800 targets per block-group
#define NGROUPS 3              // 3 * 800 = 2400 exactly -> zero lane waste
// Pad sdiff so block smem ~33.5KB: forces exactly 6 blocks/SM.
#define SDIFF_ELEMS 8448       // 33 KB (used: 30*256 = 7680)

// Scratch (allocation-free: __device__ global)
__device__ float g_diff[NROWS * KCLS];     // focal class cost diff + 2.0

// Packed f32x2 add (sm_100+): one FADD2 instead of two FADD.
__device__ __forceinline__ float2 fadd2(float2 a, float2 b) {
    unsigned long long ua, ub, ur;
    ua = *reinterpret_cast<unsigned long long*>(&a);
    ub = *reinterpret_cast<unsigned long long*>(&b);
    asm("add.rn.f32x2 %0, %1, %2;" : "=l"(ur) : "l"(ua), "l"(ub));
    return *reinterpret_cast<float2*>(&ur);
}

// ---------------------------------------------------------------------------
// Kernel 1: per-(n,k) focal classification cost diff' = pos - neg + 2
//   ln(p) = -ln(1+e^{-x}), ln(1-p) = -x - ln(1+e^{-x})  (3 MUFU not 4)
// ---------------------------------------------------------------------------
__global__ void k_diff(const float* __restrict__ logits) {
    int i = blockIdx.x * blockDim.x + threadIdx.x;   // i indexes float4
    float4 x4 = ((const float4*)logits)[i];
    float r[4];
    float xs[4] = {x4.x, x4.y, x4.z, x4.w};
    #pragma unroll
    for (int k = 0; k < 4; k++) {
        float x = xs[k];
        float e = __expf(-x);
        float a = 1.0f + e;
        float s = __logf(a);          // = -ln(p) = softplus(-x)
        float p;
        asm("rcp.approx.f32 %0, %1;" : "=f"(p) : "f"(a));   // sigmoid
        float omp = 1.0f - p;
        float pos = (omp * omp) * (0.25f * s);
        float neg = (p * p) * (0.75f * (x + s));
        r[k] = (pos - neg) + 2.0f;    // fold GIoU's "+2" constant in
    }
    ((float4*)g_diff)[i] = make_float4(r[0], r[1], r[2], r[3]);
}

// ---------------------------------------------------------------------------
// Kernel 2: main pair kernel. Block = 30 rows x 800 targets (strided TPT=5).
// Symmetric-interval identity with HALF-widths (w2 = 0.5*w):
//   mx      = max(|dcx|, |dw2|)
//   inter_w = (rw2+tw2) - mx   (SAT clamp: extents always in (0,1))
//   encl_w  = (rw2+tw2) + mx
// x/y components packed into f32x2 adds; scalar ops read the halves
// (abs folds into FADD/FMNMX input modifiers).
// ---------------------------------------------------------------------------
__global__ __launch_bounds__(BLOCK, 6) void k_main(const float* __restrict__ pboxes,
                                                   const float* __restrict__ tboxes,
                                                   const int* __restrict__ tids,
                                                   float* __restrict__ out) {
    __shared__ __align__(16) float  sdiff[SDIFF_ELEMS];   // 33 KB (padded)
    __shared__ __align__(16) float4 sbox[R_TILE];         // {cx, cy, 0.5w, 0.5h}
    __shared__ float  sarea[R_TILE];

    const int tid   = threadIdx.x;
    const int r0    = blockIdx.x * R_TILE;
    const int tbase = blockIdx.y * TT + tid;   // thread's first target; stride BLOCK

    // Stage row boxes (half-extents) + areas
    if (tid < R_TILE) {
        float4 b = ((const float4*)pboxes)[r0 + tid];
        sarea[tid] = b.z * b.w;
        sbox[tid]  = make_float4(b.x, b.y, 0.5f * b.z, 0.5f * b.w);
    }
    // Stage diff rows: 30*256 floats = 1920 float4 -> exactly 12 per thread
    {
        const float4* gd  = (const float4*)(g_diff + (size_t)r0 * KCLS);
        float4*       sd4 = (float4*)sdiff;
        #pragma unroll
        for (int i = 0; i < (R_TILE * KCLS / 4) / BLOCK; i++)
            sd4[tid + i * BLOCK] = gd[tid + i * BLOCK];
    }

    // Target data -> registers, pre-packed (and negated for f32x2 subtract).
    float2 pnc[TPT];    // {-tcx, -tcy}
    float2 pnwh[TPT];   // {-tw2, -th2}
    float2 pwh[TPT];    // { tw2,  th2}
    float  tarea[TPT];
    int    cof[TPT];
    #pragma unroll
    for (int j = 0; j < TPT; j++) {
        int t = tbase + j * BLOCK;
        float4 b = ((const float4*)tboxes)[t];
        float tw2 = 0.5f * b.z, th2 = 0.5f * b.w;
        pnc[j]  = make_float2(-b.x, -b.y);
        pnwh[j] = make_float2(-tw2, -th2);
        pwh[j]  = make_float2( tw2,  th2);
        tarea[j] = b.z * b.w;
        cof[j] = tids[t];
    }
    __syncthreads();

    float* op = out + (size_t)r0 * NTGT + tbase;

    #pragma unroll 1
    for (int r = 0; r < R_TILE; r++) {
        const float4 ra = sbox[r];        // cx cy w2 h2
        const float  rarea = sarea[r];
        const float* drow = sdiff + r * KCLS;
        const float2 pcc  = make_float2(ra.x, ra.y);   // packed row center
        const float2 pww  = make_float2(ra.z, ra.w);   // packed row half-extents
        #pragma unroll
        for (int j = 0; j < TPT; j++) {
            float d = drow[cof[j]];                    // class cost (+2)
            float2 pdc  = fadd2(pcc, pnc[j]);          // {dcx, dcy}
            float2 pdwh = fadd2(pww, pnwh[j]);         // {dw2, dh2}
            float2 psw  = fadd2(pww, pwh[j]);          // {sw2, sh2}
            // L1 on cxcywh: |dcx|+|dcy| + 2*(|dw2| + |dh2|)
            float s1 = fabsf(pdc.x)  + fabsf(pdc.y);
            float s2 = fabsf(pdwh.x) + fabsf(pdwh.y);
            float bb = __fmaf_rn(2.0f, s2, s1);
            // max terms
            float mxx = fmaxf(fabsf(pdc.x), fabsf(pdwh.x));
            float mxy = fmaxf(fabsf(pdc.y), fabsf(pdwh.y));
            // intersection / enclosing extents
            float iw = __saturatef(psw.x - mxx);
            float ih = __saturatef(psw.y - mxy);
            float ew = psw.x + mxx;
            float eh = psw.y + mxy;
            float inter = iw * ih;
            float uni   = (rarea + tarea[j]) - inter;
            float ea    = ew * eh;
            float ru, re;
            asm("rcp.approx.f32 %0, %1;" : "=f"(ru) : "f"(uni));
            asm("rcp.approx.f32 %0, %1;" : "=f"(re) : "f"(ea));
            // C = 5*bb + (class+2) - 2*(inter/uni + uni/ea)
            float t1 = uni * re;
            t1 = __fmaf_rn(inter, ru, t1);
            float c = __fmaf_rn(5.0f, bb, d);
            c = __fmaf_rn(-2.0f, t1, c);
            op[j * BLOCK] = c;
        }
        op += NTGT;
    }
}

// ---------------------------------------------------------------------------
extern "C" void kernel_launch(void* const* d_in, const int* in_sizes, int n_in,
                              void* d_out, int out_size) {
    const float* logits = (const float*)d_in[0];   // [16,1500,256]
    const float* pboxes = (const float*)d_in[1];   // [24000,4]
    const float* tboxes = (const float*)d_in[2];   // [2400,4]
    const int*   tids   = (const int*)  d_in[3];   // [2400]
    float* out = (float*)d_out;

    k_diff<<<(NROWS * KCLS) / 4 / 256, 256>>>(logits);

    dim3 grid(NROWS / R_TILE, NGROUPS);
    k_main<<<grid, BLOCK>>>(pboxes, tboxes, tids, out);
}

// round 12
// speedup vs baseline: 1.7419x; 1.0261x over previous
#include <cuda_runtime.h>
#include <cstdint>

// Problem constants
#define NROWS   24000          // BS*Q
#define NTGT    2400           // BS*NT
#define KCLS    256
#define R_TILE  30             // rows per block: grid = 800*3 = 2400
#define TPT     5              // targets per thread (strided by BLOCK)
#define BLOCK   160            // 5 warps
#define TT      (BLOCK*TPT)    // 800 targets per block-group
#define NGROUPS 3              // 3 * 800 = 2400 exactly -> zero lane waste
// Unpadded: block smem ~31.3KB -> 7 blocks/SM (35 warps, 55% theoretical occ).
#define SDIFF_ELEMS (R_TILE * KCLS)   // 7680 floats = 30 KB

// Scratch (allocation-free: __device__ global)
__device__ float g_diff[NROWS * KCLS];     // focal class cost diff + 2.0

// Packed f32x2 add (sm_100+): one FADD2 instead of two FADD.
__device__ __forceinline__ float2 fadd2(float2 a, float2 b) {
    unsigned long long ua, ub, ur;
    ua = *reinterpret_cast<unsigned long long*>(&a);
    ub = *reinterpret_cast<unsigned long long*>(&b);
    asm("add.rn.f32x2 %0, %1, %2;" : "=l"(ur) : "l"(ua), "l"(ub));
    return *reinterpret_cast<float2*>(&ur);
}

// ---------------------------------------------------------------------------
// Kernel 1: per-(n,k) focal classification cost diff' = pos - neg + 2
//   ln(p) = -ln(1+e^{-x}), ln(1-p) = -x - ln(1+e^{-x})  (3 MUFU not 4)
//   2 independent float4 chains per thread for MUFU-latency hiding.
// ---------------------------------------------------------------------------
__global__ void k_diff(const float* __restrict__ logits) {
    int i = blockIdx.x * blockDim.x + threadIdx.x;   // indexes a pair of float4
    const float4* in4 = (const float4*)logits;
    float4* out4 = (float4*)g_diff;
    float4 xa = in4[2*i], xb = in4[2*i + 1];
    float xs[8] = {xa.x, xa.y, xa.z, xa.w, xb.x, xb.y, xb.z, xb.w};
    float r[8];
    #pragma unroll
    for (int k = 0; k < 8; k++) {
        float x = xs[k];
        float e = __expf(-x);
        float a = 1.0f + e;
        float s = __logf(a);          // = -ln(p) = softplus(-x)
        float p;
        asm("rcp.approx.f32 %0, %1;" : "=f"(p) : "f"(a));   // sigmoid
        float omp = 1.0f - p;
        float pos = (omp * omp) * (0.25f * s);
        float neg = (p * p) * (0.75f * (x + s));
        r[k] = (pos - neg) + 2.0f;    // fold GIoU's "+2" constant in
    }
    out4[2*i]     = make_float4(r[0], r[1], r[2], r[3]);
    out4[2*i + 1] = make_float4(r[4], r[5], r[6], r[7]);
}

// ---------------------------------------------------------------------------
// Kernel 2: main pair kernel. Block = 30 rows x 800 targets (strided TPT=5).
// Symmetric-interval identity with HALF-widths (w2 = 0.5*w):
//   mx      = max(|dcx|, |dw2|)
//   inter_w = (rw2+tw2) - mx   (SAT clamp: extents always in (0,1))
//   encl_w  = (rw2+tw2) + mx
// ---------------------------------------------------------------------------
__global__ __launch_bounds__(BLOCK, 7) void k_main(const float* __restrict__ pboxes,
                                                   const float* __restrict__ tboxes,
                                                   const int* __restrict__ tids,
                                                   float* __restrict__ out) {
    __shared__ __align__(16) float  sdiff[SDIFF_ELEMS];   // 30 KB
    __shared__ __align__(16) float4 sbox[R_TILE];         // {cx, cy, 0.5w, 0.5h}
    __shared__ float  sarea[R_TILE];

    const int tid   = threadIdx.x;
    const int r0    = blockIdx.x * R_TILE;
    const int tbase = blockIdx.y * TT + tid;   // thread's first target; stride BLOCK

    // Stage row boxes (half-extents) + areas
    if (tid < R_TILE) {
        float4 b = ((const float4*)pboxes)[r0 + tid];
        sarea[tid] = b.z * b.w;
        sbox[tid]  = make_float4(b.x, b.y, 0.5f * b.z, 0.5f * b.w);
    }
    // Stage diff rows: 30*256 floats = 1920 float4 -> exactly 12 per thread
    {
        const float4* gd  = (const float4*)(g_diff + (size_t)r0 * KCLS);
        float4*       sd4 = (float4*)sdiff;
        #pragma unroll
        for (int i = 0; i < (R_TILE * KCLS / 4) / BLOCK; i++)
            sd4[tid + i * BLOCK] = gd[tid + i * BLOCK];
    }

    // Target data -> registers, pre-packed (and negated for f32x2 subtract).
    float2 pnc[TPT];    // {-tcx, -tcy}
    float2 pnwh[TPT];   // {-tw2, -th2}
    float2 pwh[TPT];    // { tw2,  th2}
    float  tarea[TPT];
    int    cof[TPT];
    #pragma unroll
    for (int j = 0; j < TPT; j++) {
        int t = tbase + j * BLOCK;
        float4 b = ((const float4*)tboxes)[t];
        float tw2 = 0.5f * b.z, th2 = 0.5f * b.w;
        pnc[j]  = make_float2(-b.x, -b.y);
        pnwh[j] = make_float2(-tw2, -th2);
        pwh[j]  = make_float2( tw2,  th2);
        tarea[j] = b.z * b.w;
        cof[j] = tids[t];
    }
    __syncthreads();

    float* op = out + (size_t)r0 * NTGT + tbase;

    #pragma unroll 1
    for (int r = 0; r < R_TILE; r++) {
        const float4 ra = sbox[r];        // cx cy w2 h2
        const float  rarea = sarea[r];
        const float* drow = sdiff + r * KCLS;
        const float2 pcc  = make_float2(ra.x, ra.y);   // packed row center
        const float2 pww  = make_float2(ra.z, ra.w);   // packed row half-extents
        #pragma unroll
        for (int j = 0; j < TPT; j++) {
            float d = drow[cof[j]];                    // class cost (+2)
            float2 pdc  = fadd2(pcc, pnc[j]);          // {dcx, dcy}
            float2 pdwh = fadd2(pww, pnwh[j]);         // {dw2, dh2}
            float2 psw  = fadd2(pww, pwh[j]);          // {sw2, sh2}
            // L1 on cxcywh: |dcx|+|dcy| + 2*(|dw2| + |dh2|)
            float s1 = fabsf(pdc.x)  + fabsf(pdc.y);
            float s2 = fabsf(pdwh.x) + fabsf(pdwh.y);
            float bb = __fmaf_rn(2.0f, s2, s1);
            // max terms
            float mxx = fmaxf(fabsf(pdc.x), fabsf(pdwh.x));
            float mxy = fmaxf(fabsf(pdc.y), fabsf(pdwh.y));
            // intersection / enclosing extents
            float iw = __saturatef(psw.x - mxx);
            float ih = __saturatef(psw.y - mxy);
            float ew = psw.x + mxx;
            float eh = psw.y + mxy;
            float inter = iw * ih;
            float uni   = (rarea + tarea[j]) - inter;
            float ea    = ew * eh;
            float ru, re;
            asm("rcp.approx.f32 %0, %1;" : "=f"(ru) : "f"(uni));
            asm("rcp.approx.f32 %0, %1;" : "=f"(re) : "f"(ea));
            // C = 5*bb + (class+2) - 2*(inter/uni + uni/ea)
            float t1 = uni * re;
            t1 = __fmaf_rn(inter, ru, t1);
            float c = __fmaf_rn(5.0f, bb, d);
            c = __fmaf_rn(-2.0f, t1, c);
            op[j * BLOCK] = c;
        }
        op += NTGT;
    }
}

// ---------------------------------------------------------------------------
extern "C" void kernel_launch(void* const* d_in, const int* in_sizes, int n_in,
                              void* d_out, int out_size) {
    const float* logits = (const float*)d_in[0];   // [16,1500,256]
    const float* pboxes = (const float*)d_in[1];   // [24000,4]
    const float* tboxes = (const float*)d_in[2];   // [2400,4]
    const int*   tids   = (const int*)  d_in[3];   // [2400]
    float* out = (float*)d_out;

    // 6,144,000 elems / 8 per thread / 256 per block = 3000 blocks
    k_diff<<<(NROWS * KCLS) / 8 / 256, 256>>>(logits);

    dim3 grid(NROWS / R_TILE, NGROUPS);
    k_main<<<grid, BLOCK>>>(pboxes, tboxes, tids, out);
}

// round 14
// speedup vs baseline: 1.7508x; 1.0051x over previous
#include <cuda_runtime.h>
#include <cstdint>

// Problem constants
#define NROWS   24000          // BS*Q
#define NTGT    2400           // BS*NT
#define KCLS    256
#define R_TILE  30             // rows per block: grid = 800*3 = 2400
#define BLOCK   160            // 5 warps
#define TT      800            // targets per block-group (2 pairs *320 + 160 tail)
#define NGROUPS 3              // 3 * 800 = 2400 exactly -> zero lane waste
#define SDIFF_ELEMS (R_TILE * KCLS)   // 7680 floats = 30 KB

// Scratch (allocation-free: __device__ global)
__device__ float g_diff[NROWS * KCLS];     // focal class cost diff + 2.0

// ---- Packed f32x2 helpers (sm_100+). Operands are 64-bit register pairs. ----
__device__ __forceinline__ float2 fadd2(float2 a, float2 b) {
    unsigned long long ua = *reinterpret_cast<unsigned long long*>(&a);
    unsigned long long ub = *reinterpret_cast<unsigned long long*>(&b);
    unsigned long long ur;
    asm("add.rn.f32x2 %0, %1, %2;" : "=l"(ur) : "l"(ua), "l"(ub));
    return *reinterpret_cast<float2*>(&ur);
}
__device__ __forceinline__ float2 fmul2(float2 a, float2 b) {
    unsigned long long ua = *reinterpret_cast<unsigned long long*>(&a);
    unsigned long long ub = *reinterpret_cast<unsigned long long*>(&b);
    unsigned long long ur;
    asm("mul.rn.f32x2 %0, %1, %2;" : "=l"(ur) : "l"(ua), "l"(ub));
    return *reinterpret_cast<float2*>(&ur);
}
__device__ __forceinline__ float2 ffma2(float2 a, float2 b, float2 c) {
    unsigned long long ua = *reinterpret_cast<unsigned long long*>(&a);
    unsigned long long ub = *reinterpret_cast<unsigned long long*>(&b);
    unsigned long long uc = *reinterpret_cast<unsigned long long*>(&c);
    unsigned long long ur;
    asm("fma.rn.f32x2 %0, %1, %2, %3;" : "=l"(ur) : "l"(ua), "l"(ub), "l"(uc));
    return *reinterpret_cast<float2*>(&ur);
}

// ---------------------------------------------------------------------------
// Kernel 1: per-(n,k) focal classification cost diff' = pos - neg + 2
// ---------------------------------------------------------------------------
__global__ void k_diff(const float* __restrict__ logits) {
    int i = blockIdx.x * blockDim.x + threadIdx.x;   // indexes a pair of float4
    const float4* in4 = (const float4*)logits;
    float4* out4 = (float4*)g_diff;
    float4 xa = in4[2*i], xb = in4[2*i + 1];
    float xs[8] = {xa.x, xa.y, xa.z, xa.w, xb.x, xb.y, xb.z, xb.w};
    float r[8];
    #pragma unroll
    for (int k = 0; k < 8; k++) {
        float x = xs[k];
        float e = __expf(-x);
        float a = 1.0f + e;
        float s = __logf(a);          // = -ln(p) = softplus(-x)
        float p;
        asm("rcp.approx.f32 %0, %1;" : "=f"(p) : "f"(a));   // sigmoid
        float omp = 1.0f - p;
        float pos = (omp * omp) * (0.25f * s);
        float neg = (p * p) * (0.75f * (x + s));
        r[k] = (pos - neg) + 2.0f;    // fold GIoU's "+2" constant in
    }
    out4[2*i]     = make_float4(r[0], r[1], r[2], r[3]);
    out4[2*i + 1] = make_float4(r[4], r[5], r[6], r[7]);
}

// ---------------------------------------------------------------------------
// Kernel 2: main pair kernel. Block = 30 rows x 800 targets.
// Target map per thread: pairs {2tid, 2tid+1} + 320p for p=0,1 (adjacent ->
// STG.64) plus scalar tail at 640 + tid. 160*(2+2+1) = 800, zero waste.
// All plain arithmetic is packed f32x2 ACROSS the target pair; abs/max/sat
// stay scalar (free SASS modifiers) reading the packed halves.
// ---------------------------------------------------------------------------
__global__ __launch_bounds__(BLOCK) void k_main(const float* __restrict__ pboxes,
                                                const float* __restrict__ tboxes,
                                                const int* __restrict__ tids,
                                                float* __restrict__ out) {
    __shared__ __align__(16) float  sdiff[SDIFF_ELEMS];   // 30 KB
    __shared__ __align__(16) float4 sbox[R_TILE];         // {cx, cy, 0.5w, 0.5h}
    __shared__ float  sarea[R_TILE];

    const int tid   = threadIdx.x;
    const int r0    = blockIdx.x * R_TILE;
    const int gbase = blockIdx.y * TT;

    // Stage row boxes (half-extents) + areas
    if (tid < R_TILE) {
        float4 b = ((const float4*)pboxes)[r0 + tid];
        sarea[tid] = b.z * b.w;
        sbox[tid]  = make_float4(b.x, b.y, 0.5f * b.z, 0.5f * b.w);
    }
    // Stage diff rows: 30*256 floats = 1920 float4 -> exactly 12 per thread
    {
        const float4* gd  = (const float4*)(g_diff + (size_t)r0 * KCLS);
        float4*       sd4 = (float4*)sdiff;
        #pragma unroll
        for (int i = 0; i < (R_TILE * KCLS / 4) / BLOCK; i++)
            sd4[tid + i * BLOCK] = gd[tid + i * BLOCK];
    }

    // ---- Target registers ----
    // Pairs p=0,1: targets a = gbase + 320p + 2tid, b = a+1 (packed as {a,b}).
    float2 ncx[2], ncy[2], nw2[2], nh2[2], w2v[2], h2v[2], ta2[2];
    int    ida[2], idb[2];
    #pragma unroll
    for (int p = 0; p < 2; p++) {
        int t = gbase + 320 * p + 2 * tid;
        float4 ba = ((const float4*)tboxes)[t];
        float4 bb = ((const float4*)tboxes)[t + 1];
        ncx[p] = make_float2(-ba.x, -bb.x);
        ncy[p] = make_float2(-ba.y, -bb.y);
        nw2[p] = make_float2(-0.5f * ba.z, -0.5f * bb.z);
        nh2[p] = make_float2(-0.5f * ba.w, -0.5f * bb.w);
        w2v[p] = make_float2( 0.5f * ba.z,  0.5f * bb.z);
        h2v[p] = make_float2( 0.5f * ba.w,  0.5f * bb.w);
        ta2[p] = make_float2(ba.z * ba.w, bb.z * bb.w);
        ida[p] = tids[t];
        idb[p] = tids[t + 1];
    }
    // Scalar tail: target gbase + 640 + tid
    float s_ncx, s_ncy, s_nw2, s_nh2, s_w2, s_h2, s_ta;
    int   s_id;
    {
        int t = gbase + 640 + tid;
        float4 b = ((const float4*)tboxes)[t];
        s_ncx = -b.x; s_ncy = -b.y;
        s_nw2 = -0.5f * b.z; s_nh2 = -0.5f * b.w;
        s_w2  =  0.5f * b.z; s_h2  =  0.5f * b.w;
        s_ta  = b.z * b.w;
        s_id  = tids[t];
    }
    __syncthreads();

    const float2 negone2 = make_float2(-1.0f, -1.0f);
    const float2 negtwo2 = make_float2(-2.0f, -2.0f);
    const float2 two2    = make_float2( 2.0f,  2.0f);

    float* oprow = out + (size_t)r0 * NTGT + gbase;

    #pragma unroll 1
    for (int r = 0; r < R_TILE; r++) {
        const float4 ra = sbox[r];          // cx cy w2 h2
        const float  rarea = sarea[r];
        const float* drow = sdiff + r * KCLS;
        // Row constants duplicated into both f32x2 lanes
        const float2 rcx2 = make_float2(ra.x, ra.x);
        const float2 rcy2 = make_float2(ra.y, ra.y);
        const float2 rw22 = make_float2(ra.z, ra.z);
        const float2 rh22 = make_float2(ra.w, ra.w);
        const float2 rar2 = make_float2(rarea, rarea);

        #pragma unroll
        for (int p = 0; p < 2; p++) {
            float da = drow[ida[p]];
            float db = drow[idb[p]];
            float2 dcx = fadd2(rcx2, ncx[p]);
            float2 dcy = fadd2(rcy2, ncy[p]);
            float2 dw  = fadd2(rw22, nw2[p]);
            float2 dh  = fadd2(rh22, nh2[p]);
            float2 sw  = fadd2(rw22, w2v[p]);
            float2 sh  = fadd2(rh22, h2v[p]);
            // scalar abs-sums (abs folds into FADD modifiers)
            float2 s12 = make_float2(fabsf(dcx.x) + fabsf(dcy.x),
                                     fabsf(dcx.y) + fabsf(dcy.y));
            float2 s22 = make_float2(fabsf(dw.x) + fabsf(dh.x),
                                     fabsf(dw.y) + fabsf(dh.y));
            float2 bb2 = ffma2(two2, s22, s12);
            // max terms (scalar FMNMX, abs modifiers)
            float2 mx = make_float2(fmaxf(fabsf(dcx.x), fabsf(dw.x)),
                                    fmaxf(fabsf(dcx.y), fabsf(dw.y)));
            float2 my = make_float2(fmaxf(fabsf(dcy.x), fabsf(dh.x)),
                                    fmaxf(fabsf(dcy.y), fabsf(dh.y)));
            // intersection extents (scalar FADD.SAT; extents always < 1)
            float2 iw2 = make_float2(__saturatef(sw.x - mx.x),
                                     __saturatef(sw.y - mx.y));
            float2 ih2 = make_float2(__saturatef(sh.x - my.x),
                                     __saturatef(sh.y - my.y));
            // enclosing extents (packed)
            float2 ew2 = fadd2(sw, mx);
            float2 eh2 = fadd2(sh, my);
            float2 inter = fmul2(iw2, ih2);
            float2 su    = fadd2(rar2, ta2[p]);
            float2 uni   = ffma2(inter, negone2, su);
            float2 ea    = fmul2(ew2, eh2);
            float rua, rub, rea, reb;
            asm("rcp.approx.f32 %0, %1;" : "=f"(rua) : "f"(uni.x));
            asm("rcp.approx.f32 %0, %1;" : "=f"(rub) : "f"(uni.y));
            asm("rcp.approx.f32 %0, %1;" : "=f"(rea) : "f"(ea.x));
            asm("rcp.approx.f32 %0, %1;" : "=f"(reb) : "f"(ea.y));
            float2 ru2 = make_float2(rua, rub);
            float2 re2 = make_float2(rea, reb);
            float2 t12 = ffma2(inter, ru2, fmul2(uni, re2));
            float2 cp  = make_float2(__fmaf_rn(5.0f, bb2.x, da),
                                     __fmaf_rn(5.0f, bb2.y, db));
            float2 res = ffma2(negtwo2, t12, cp);
            *(float2*)(oprow + 320 * p + 2 * tid) = res;   // STG.64, coalesced
        }
        // ---- scalar tail target ----
        {
            float d = drow[s_id];
            float dcx = ra.x + s_ncx, dcy = ra.y + s_ncy;
            float dw  = ra.z + s_nw2, dh  = ra.w + s_nh2;
            float sw  = ra.z + s_w2,  sh  = ra.w + s_h2;
            float s1 = fabsf(dcx) + fabsf(dcy);
            float s2 = fabsf(dw)  + fabsf(dh);
            float bb = __fmaf_rn(2.0f, s2, s1);
            float mxx = fmaxf(fabsf(dcx), fabsf(dw));
            float mxy = fmaxf(fabsf(dcy), fabsf(dh));
            float iw = __saturatef(sw - mxx);
            float ih = __saturatef(sh - mxy);
            float ew = sw + mxx, eh = sh + mxy;
            float inter = iw * ih;
            float uni   = (rarea + s_ta) - inter;
            float ea    = ew * eh;
            float ru, re;
            asm("rcp.approx.f32 %0, %1;" : "=f"(ru) : "f"(uni));
            asm("rcp.approx.f32 %0, %1;" : "=f"(re) : "f"(ea));
            float t1 = __fmaf_rn(inter, ru, uni * re);
            float c  = __fmaf_rn(5.0f, bb, d);
            oprow[640 + tid] = __fmaf_rn(-2.0f, t1, c);
        }
        oprow += NTGT;
    }
}

// ---------------------------------------------------------------------------
extern "C" void kernel_launch(void* const* d_in, const int* in_sizes, int n_in,
                              void* d_out, int out_size) {
    const float* logits = (const float*)d_in[0];   // [16,1500,256]
    const float* pboxes = (const float*)d_in[1];   // [24000,4]
    const float* tboxes = (const float*)d_in[2];   // [2400,4]
    const int*   tids   = (const int*)  d_in[3];   // [2400]
    float* out = (float*)d_out;

    // 6,144,000 elems / 8 per thread / 256 per block = 3000 blocks
    k_diff<<<(NROWS * KCLS) / 8 / 256, 256>>>(logits);

    dim3 grid(NROWS / R_TILE, NGROUPS);
    k_main<<<grid, BLOCK>>>(pboxes, tboxes, tids, out);
}